// round 12
// baseline (speedup 1.0000x reference)
#include <cuda_runtime.h>
#include <cuda_bf16.h>
#include <cstdint>
#include <math.h>

#define NU 50000
#define NI 50000
#define N5 50000
#define HD 128
#define NE 800000
#define NG 512
#define NC 16
#define NL 3
#define BN_EPS 1e-5f

#define CDIV(a,b) (((a)+(b)-1)/(b))

// ---------------- scratch (static device globals; no runtime alloc) -------------
__device__ float  g_xu[(size_t)NU*HD];
__device__ float  g_xi[(size_t)NI*HD];
__device__ float  g_newu[(size_t)NU*HD];
__device__ float  g_newi[(size_t)NI*HD];
__device__ float  g_aggu[(size_t)NU*HD];
__device__ float  g_aggi[(size_t)NI*HD];
__device__ char   g_wpre[(size_t)NL*2*131072];  // [layer][side][h][hi|lo] 4x32KB
__device__ int    g_rowi[NI+1];
__device__ int    g_rowu[NU+1];
__device__ int    g_col_u2i[NE];
__device__ int    g_col_i2u[NE];
__device__ int    g_degi[NI];
__device__ int    g_degu[NU];
__device__ int    g_curi[NI];
__device__ int    g_curu[NU];
__device__ float  g_stats[NL*2*2*HD];
__device__ int    g_su[NG+1];
__device__ int    g_si[NG+1];

// =================== helpers ====================================================
__device__ __forceinline__ uint32_t smem_u32(const void* p) {
    uint32_t a;
    asm("{ .reg .u64 t; cvta.to.shared.u64 t, %1; cvt.u32.u64 %0, t; }" : "=r"(a) : "l"(p));
    return a;
}
__device__ __forceinline__ void ldsm4(uint32_t* r, uint32_t addr) {
    asm volatile("ldmatrix.sync.aligned.m8n8.x4.shared.b16 {%0,%1,%2,%3}, [%4];"
        : "=r"(r[0]), "=r"(r[1]), "=r"(r[2]), "=r"(r[3]) : "r"(addr));
}
__device__ __forceinline__ void mma16816(float* d, const uint32_t* a, const uint32_t* b) {
    asm volatile(
        "mma.sync.aligned.m16n8k16.row.col.f32.bf16.bf16.f32 "
        "{%0,%1,%2,%3}, {%4,%5,%6,%7}, {%8,%9}, {%0,%1,%2,%3};"
        : "+f"(d[0]), "+f"(d[1]), "+f"(d[2]), "+f"(d[3])
        : "r"(a[0]), "r"(a[1]), "r"(a[2]), "r"(a[3]), "r"(b[0]), "r"(b[1]));
}
__device__ __forceinline__ void split2(float a, float b, uint32_t& hi, uint32_t& lo) {
    __nv_bfloat16 ah = __float2bfloat16(a);
    __nv_bfloat16 bh = __float2bfloat16(b);
    __nv_bfloat16 al = __float2bfloat16(a - __bfloat162float(ah));
    __nv_bfloat16 bl = __float2bfloat16(b - __bfloat162float(bh));
    hi = (uint32_t)__bfloat16_as_ushort(ah) | ((uint32_t)__bfloat16_as_ushort(bh) << 16);
    lo = (uint32_t)__bfloat16_as_ushort(al) | ((uint32_t)__bfloat16_as_ushort(bl) << 16);
}

// ---------------- merged setup kernels ------------------------------------------
__global__ void k_init(float* stats, int* degi, int* degu, int* curi, int* curu) {
    int i = blockIdx.x * blockDim.x + threadIdx.x;
    if (i < NL*2*2*HD) stats[i] = 0.f;
    if (i < NI) { degi[i] = 0; curi[i] = 0; }
    if (i < NU) { degu[i] = 0; curu[i] = 0; }
}
__global__ void k_hist2(const int* __restrict__ dsti, const int* __restrict__ dstu,
                        int* __restrict__ degi, int* __restrict__ degu) {
    int e = blockIdx.x * blockDim.x + threadIdx.x;
    if (e < NE) atomicAdd(&degi[dsti[e]], 1);
    else if (e < 2*NE) atomicAdd(&degu[dstu[e - NE]], 1);
}
__device__ void scan_one(const int* __restrict__ deg, int n, int* __restrict__ row) {
    __shared__ int part[1024];
    int t = threadIdx.x;
    int chunk = (n + 1023) / 1024;
    int s0 = t * chunk, s1 = min(s0 + chunk, n);
    int sum = 0;
    for (int i = s0; i < s1; i++) sum += deg[i];
    part[t] = sum;
    __syncthreads();
    for (int d = 1; d < 1024; d <<= 1) {
        int v = 0;
        if (t >= d) v = part[t - d];
        __syncthreads();
        if (t >= d) part[t] += v;
        __syncthreads();
    }
    int excl = (t == 0) ? 0 : part[t - 1];
    for (int i = s0; i < s1; i++) { row[i] = excl; excl += deg[i]; }
    if (t == 1023) row[n] = excl;
}
__global__ void k_scan2(const int* __restrict__ degi, int* __restrict__ rowi,
                        const int* __restrict__ degu, int* __restrict__ rowu) {
    if (blockIdx.x == 0) scan_one(degi, NI, rowi);
    else                 scan_one(degu, NU, rowu);
}
__global__ void k_scatter2(const int* __restrict__ ei, const int* __restrict__ eu,
                           const int* __restrict__ rowi, int* __restrict__ curi,
                           int* __restrict__ coli,
                           const int* __restrict__ rowu, int* __restrict__ curu,
                           int* __restrict__ colu) {
    int e = blockIdx.x * blockDim.x + threadIdx.x;
    if (e < NE) {
        int d = ei[NE + e];
        int p = rowi[d] + atomicAdd(&curi[d], 1);
        coli[p] = ei[e];
    } else if (e < 2*NE) {
        int ee = e - NE;
        int d = eu[NE + ee];
        int p = rowu[d] + atomicAdd(&curu[d], 1);
        colu[p] = eu[ee];
    }
}
__global__ void k_offsets2(const int* __restrict__ bu, const int* __restrict__ bi,
                           int* __restrict__ su, int* __restrict__ si) {
    int i = blockIdx.x * blockDim.x + threadIdx.x;
    int g = (i <= NG) ? i : i - (NG + 1);
    if (g > NG || i > 2*NG + 1) return;
    const int* batch = (i <= NG) ? bu : bi;
    int* off = (i <= NG) ? su : si;
    int lo = 0, hi = N5;
    while (lo < hi) { int mid = (lo + hi) >> 1; if (batch[mid] < g) lo = mid + 1; else hi = mid; }
    off[g] = lo;
}

// ---------------- weight preconversion into the gemm's swizzled smem layout -----
__global__ void k_prepw(const float* __restrict__ Wrel_u2i, const float* __restrict__ Wroot_u2i,
                        const float* __restrict__ Wrel_i2u, const float* __restrict__ Wroot_i2u,
                        char* __restrict__ wpre) {
    int idx = blockIdx.x * blockDim.x + threadIdx.x;
    if (idx >= NL * 2 * 2 * 128 * 64) return;       // (l, side, h, n, pair)
    int pair = idx & 63;
    int n    = (idx >> 6) & 127;
    int h    = (idx >> 13) & 1;
    int side = (idx >> 14) & 1;
    int l    = idx >> 15;
    const float* W = (side == 0) ? (h ? Wroot_u2i : Wrel_u2i)
                                 : (h ? Wroot_i2u : Wrel_i2u);
    W += (size_t)l * HD * HD + (size_t)n * HD + pair * 2;
    uint32_t hi, lo;
    split2(W[0], W[1], hi, lo);
    int k = pair * 2;
    int c = k >> 3;
    int off = n * 256 + ((c ^ (n & 7)) << 4) + (k & 7) * 2;
    size_t base = ((size_t)l * 2 + side) * 131072;
    *(uint32_t*)(wpre + base + (size_t)(h * 2 + 0) * 32768 + off) = hi;
    *(uint32_t*)(wpre + base + (size_t)(h * 2 + 1) * 32768 + off) = lo;
}

// ---------------- aggregation: 2 warps per node, 64 channels each ---------------
__device__ __forceinline__ void agg_half(const int* __restrict__ rowp,
                                         const int* __restrict__ col,
                                         const float* __restrict__ src,
                                         float* __restrict__ dst,
                                         int node, int half, int lane) {
    int s = rowp[node], e = rowp[node + 1];
    float2 acc = make_float2(0.f, 0.f);
    const float* base = src + half * 64 + lane * 2;
    for (int j = s; j < e; j += 32) {
        int m = min(32, e - j);
        int idx = (lane < m) ? col[j + lane] : 0;
        for (int t = 0; t < m; t++) {
            int sidx = __shfl_sync(0xffffffffu, idx, t);
            float2 v = *(const float2*)(base + (size_t)sidx * HD);
            acc.x += v.x; acc.y += v.y;
        }
    }
    *(float2*)(dst + (size_t)node * HD + half * 64 + lane * 2) = acc;
}

__global__ void k_agg2(const int* __restrict__ rowi, const int* __restrict__ coli,
                       const float* __restrict__ srcU, float* __restrict__ dstI,
                       const int* __restrict__ rowu, const int* __restrict__ colu,
                       const float* __restrict__ srcI, float* __restrict__ dstU) {
    int w = (blockIdx.x * blockDim.x + threadIdx.x) >> 5;
    int lane = threadIdx.x & 31;
    if (w < 2*NI) {
        agg_half(rowi, coli, srcU, dstI, w >> 1, w & 1, lane);
    } else if (w < 2*(NI + NU)) {
        int w2 = w - 2*NI;
        agg_half(rowu, colu, srcI, dstU, w2 >> 1, w2 & 1, lane);
    }
}

// ============== mma.sync GEMM (R5 structure), preconverted weights ==============
#define A_HI 0
#define A_LO 32768
#define B_HI 65536
#define B_LO 98304
#define SMF_STRIDE 136
#define SSUM_OFF 100352
#define SSQ_OFF  100864
#define AFF_OFF  131072
#define GEMM_SMEM (131072 + 2560)

struct GemmSide {
    const float* agg;
    const float* xprev;
    const char*  wpre;
    const float* bias;
    float*       out;
    float*       statsAcc;
    const int*   rowp;
    const float* statsS;  const float* gS; const float* bS;
    const float* statsD;  const float* gD; const float* bD;
};

__global__ __launch_bounds__(256, 1)
void k_gemm2(GemmSide SI, GemmSide SU, int nblk0, int use_affine)
{
    extern __shared__ __align__(128) char smem[];
    uint32_t sb = smem_u32(smem);
    int tid = threadIdx.x;
    int lane = tid & 31, warp = tid >> 5;
    int warpM = warp & 3, warpN = warp >> 2;

    const GemmSide& S = (blockIdx.x < nblk0) ? SI : SU;
    int row0 = ((blockIdx.x < nblk0) ? blockIdx.x : blockIdx.x - nblk0) * 128;

    float* affSa = (float*)(smem + AFF_OFF);
    float* affSb = affSa + 128;
    float* affDa = affSb + 128;
    float* affDb = affDa + 128;
    float* degf  = affDb + 128;
    if (tid < 128) {
        float sa0 = 1.f, sb0 = 0.f, sa1 = 1.f, sb1 = 0.f;
        if (use_affine) {
            const float invN = 1.f / (float)N5;
            float m = S.statsS[tid] * invN;
            float var = S.statsS[HD + tid] * invN - m * m;
            float a = S.gS[tid] * rsqrtf(fmaxf(var, 0.f) + BN_EPS);
            sa0 = a; sb0 = S.bS[tid] - m * a;
            m = S.statsD[tid] * invN;
            var = S.statsD[HD + tid] * invN - m * m;
            a = S.gD[tid] * rsqrtf(fmaxf(var, 0.f) + BN_EPS);
            sa1 = a; sb1 = S.bD[tid] - m * a;
        }
        affSa[tid] = sa0; affSb[tid] = sb0; affDa[tid] = sa1; affDb[tid] = sb1;
    } else {
        int r = tid - 128;
        int gr = row0 + r;
        degf[r] = (gr < N5) ? (float)(S.rowp[gr + 1] - S.rowp[gr]) : 0.f;
    }
    __syncthreads();

    int mi = lane >> 3;
    int lr = lane & 7;
    int a_kmi = mi >> 1;
    uint32_t a_off[2], a_xor[2];
#pragma unroll
    for (int mt = 0; mt < 2; mt++) {
        int r = warpM * 32 + mt * 16 + (mi & 1) * 8 + lr;
        a_off[mt] = r * 256;
        a_xor[mt] = r & 7;
    }
    int b_kmi = mi & 1;
    uint32_t b_off[4], b_xor[4];
#pragma unroll
    for (int jj = 0; jj < 4; jj++) {
        int r = warpN * 64 + jj * 16 + (mi >> 1) * 8 + lr;
        b_off[jj] = r * 256;
        b_xor[jj] = r & 7;
    }

    float acc[2][8][4];
#pragma unroll
    for (int mt = 0; mt < 2; mt++)
#pragma unroll
        for (int j = 0; j < 8; j++)
#pragma unroll
            for (int t = 0; t < 4; t++) acc[mt][j][t] = 0.f;

    for (int h = 0; h < 2; h++) {
        if (h) __syncthreads();
        const float* As = h ? S.xprev : S.agg;
        const float* ka = h ? affDa : affSa;
        const float* kb = h ? affDb : affSb;
        // fill A tile: affine + bf16 hi/lo split, chunk-swizzled
#pragma unroll
        for (int i = 0; i < 8; i++) {
            int lin = tid + i * 256;
            int r = lin >> 4, c = lin & 15;
            int gr = row0 + r;
            float ds = h ? 1.f : degf[r];
            float4 v0 = make_float4(0.f,0.f,0.f,0.f), v1 = v0;
            if (gr < N5) {
                v0 = *(const float4*)(As + (size_t)gr * HD + c * 8);
                v1 = *(const float4*)(As + (size_t)gr * HD + c * 8 + 4);
            }
            float4 ka0 = *(const float4*)&ka[c * 8];
            float4 ka1 = *(const float4*)&ka[c * 8 + 4];
            float4 kb0 = *(const float4*)&kb[c * 8];
            float4 kb1 = *(const float4*)&kb[c * 8 + 4];
            v0.x = ka0.x * v0.x + ds * kb0.x;
            v0.y = ka0.y * v0.y + ds * kb0.y;
            v0.z = ka0.z * v0.z + ds * kb0.z;
            v0.w = ka0.w * v0.w + ds * kb0.w;
            v1.x = ka1.x * v1.x + ds * kb1.x;
            v1.y = ka1.y * v1.y + ds * kb1.y;
            v1.z = ka1.z * v1.z + ds * kb1.z;
            v1.w = ka1.w * v1.w + ds * kb1.w;
            uint32_t h0,l0,h1,l1,h2,l2,h3,l3;
            split2(v0.x, v0.y, h0, l0); split2(v0.z, v0.w, h1, l1);
            split2(v1.x, v1.y, h2, l2); split2(v1.z, v1.w, h3, l3);
            int off = r * 256 + ((c ^ (r & 7)) << 4);
            *(uint4*)(smem + A_HI + off) = make_uint4(h0, h1, h2, h3);
            *(uint4*)(smem + A_LO + off) = make_uint4(l0, l1, l2, l3);
        }
        // fill B tile: straight uint4 copy of preconverted blocks
        {
            const uint4* srcH = (const uint4*)(S.wpre + (size_t)(h * 2 + 0) * 32768);
            const uint4* srcL = (const uint4*)(S.wpre + (size_t)(h * 2 + 1) * 32768);
            uint4* dH = (uint4*)(smem + B_HI);
            uint4* dL = (uint4*)(smem + B_LO);
#pragma unroll
            for (int i = 0; i < 8; i++) {
                dH[tid + i * 256] = srcH[tid + i * 256];
                dL[tid + i * 256] = srcL[tid + i * 256];
            }
        }
        __syncthreads();

#pragma unroll
        for (int p = 0; p < 3; p++) {
            uint32_t bA = sb + ((p == 1) ? A_LO : A_HI);
            uint32_t bB = sb + ((p == 2) ? B_LO : B_HI);
#pragma unroll
            for (int ks = 0; ks < 8; ks++) {
                uint32_t afr[2][4];
#pragma unroll
                for (int mt = 0; mt < 2; mt++) {
                    uint32_t ck = (uint32_t)((ks << 1) | a_kmi) ^ a_xor[mt];
                    ldsm4(afr[mt], bA + a_off[mt] + (ck << 4));
                }
                uint32_t bfr[8][2];
#pragma unroll
                for (int jj = 0; jj < 4; jj++) {
                    uint32_t q[4];
                    uint32_t ck = (uint32_t)((ks << 1) | b_kmi) ^ b_xor[jj];
                    ldsm4(q, bB + b_off[jj] + (ck << 4));
                    bfr[2*jj][0] = q[0]; bfr[2*jj][1] = q[1];
                    bfr[2*jj+1][0] = q[2]; bfr[2*jj+1][1] = q[3];
                }
#pragma unroll
                for (int mt = 0; mt < 2; mt++)
#pragma unroll
                    for (int j = 0; j < 8; j++)
                        mma16816(acc[mt][j], afr[mt], bfr[j]);
            }
        }
    }
    __syncthreads();

    float* smF = (float*)smem;
    float* ssum = (float*)(smem + SSUM_OFF);
    float* ssq  = (float*)(smem + SSQ_OFF);
    if (tid < 128) { ssum[tid] = 0.f; ssq[tid] = 0.f; }
#pragma unroll
    for (int mt = 0; mt < 2; mt++) {
        int r0 = warpM * 32 + mt * 16 + (lane >> 2);
        int c  = warpN * 64 + (lane & 3) * 2;
#pragma unroll
        for (int j = 0; j < 8; j++) {
            int cc = c + j * 8;
            *(float2*)&smF[r0 * SMF_STRIDE + cc]       = make_float2(acc[mt][j][0], acc[mt][j][1]);
            *(float2*)&smF[(r0 + 8) * SMF_STRIDE + cc] = make_float2(acc[mt][j][2], acc[mt][j][3]);
        }
    }
    __syncthreads();

    // bias + relu + store + BN stats
    {
        int c4 = tid & 31, rg = tid >> 5;
        float4 bv = *(const float4*)(S.bias + c4 * 4);
        float s0=0,s1=0,s2=0,s3=0,q0=0,q1=0,q2=0,q3=0;
#pragma unroll
        for (int it = 0; it < 16; it++) {
            int r = it * 8 + rg;
            int gr = row0 + r;
            if (gr < N5) {
                float4 v = *(float4*)&smF[r * SMF_STRIDE + c4 * 4];
                v.x = fmaxf(v.x + bv.x, 0.f);
                v.y = fmaxf(v.y + bv.y, 0.f);
                v.z = fmaxf(v.z + bv.z, 0.f);
                v.w = fmaxf(v.w + bv.w, 0.f);
                *(float4*)(S.out + (size_t)gr * HD + c4 * 4) = v;
                s0 += v.x; s1 += v.y; s2 += v.z; s3 += v.w;
                q0 += v.x*v.x; q1 += v.y*v.y; q2 += v.z*v.z; q3 += v.w*v.w;
            }
        }
        atomicAdd(&ssum[c4*4+0], s0); atomicAdd(&ssum[c4*4+1], s1);
        atomicAdd(&ssum[c4*4+2], s2); atomicAdd(&ssum[c4*4+3], s3);
        atomicAdd(&ssq[c4*4+0], q0);  atomicAdd(&ssq[c4*4+1], q1);
        atomicAdd(&ssq[c4*4+2], q2);  atomicAdd(&ssq[c4*4+3], q3);
    }
    __syncthreads();
    if (tid < 128) {
        atomicAdd(&S.statsAcc[tid], ssum[tid]);
        atomicAdd(&S.statsAcc[HD + tid], ssq[tid]);
    }
}

// ---------------- pooling: 512 threads, 4-way row split + smem reduce -----------
__global__ __launch_bounds__(512)
void k_pool(const float* __restrict__ xu, const float* __restrict__ xi,
            const int* __restrict__ su, const int* __restrict__ si,
            const float* __restrict__ statsU, const float* __restrict__ gU,
            const float* __restrict__ btU,
            const float* __restrict__ statsI, const float* __restrict__ gI,
            const float* __restrict__ btI,
            float* __restrict__ feats) {
    __shared__ float red[512];
    int g = blockIdx.x;
    int tid = threadIdx.x;
    int c = tid & 127;
    int chunk = tid >> 7;       // 0..3

    int u0 = su[g], u1 = su[g + 1];
    int i0 = si[g], i1 = si[g + 1];
    float sumU = 0.f, sumI = 0.f;
    for (int r = u0 + chunk; r < u1; r += 4) sumU += xu[(size_t)r * HD + c];
    for (int r = i0 + chunk; r < i1; r += 4) sumI += xi[(size_t)r * HD + c];
    red[tid] = sumU;
    __syncthreads();
    if (chunk == 0) sumU = red[c] + red[128 + c] + red[256 + c] + red[384 + c];
    __syncthreads();
    red[tid] = sumI;
    __syncthreads();
    if (chunk == 0) {
        sumI = red[c] + red[128 + c] + red[256 + c] + red[384 + c];
        const float invN = 1.f / (float)N5;
        float mU = statsU[c] * invN;
        float vU = statsU[HD + c] * invN - mU * mU;
        float aU = gU[c] * rsqrtf(fmaxf(vU, 0.f) + BN_EPS);
        float bU = btU[c] - mU * aU;
        float mI = statsI[c] * invN;
        float vI = statsI[HD + c] * invN - mI * mI;
        float aI = gI[c] * rsqrtf(fmaxf(vI, 0.f) + BN_EPS);
        float bI = btI[c] - mI * aI;
        float nu = (float)(u1 - u0), ni = (float)(i1 - i0);
        float cnt = fmaxf(nu + ni, 1.f);
        feats[(size_t)g * HD + c] = (aU * sumU + nu * bU + aI * sumI + ni * bI) / cnt;
    }
}

// ---------------- per-layer classifier heads ------------------------------------
__global__ void k_logits(const float* __restrict__ feats, const float* __restrict__ fcW,
                         const float* __restrict__ fcb, float* __restrict__ logits) {
    int idx = blockIdx.x * blockDim.x + threadIdx.x;
    if (idx >= NL * NG * NC) return;
    int l = idx / (NG * NC);
    int g = (idx / NC) % NG;
    int c = idx % NC;
    const float* f = feats + ((size_t)l * NG + g) * HD;
    const float* w = fcW + ((size_t)l * NC + c) * HD;
    float sum = fcb[l * NC + c];
#pragma unroll
    for (int k = 0; k < HD; k += 4) {
        float4 a = *(const float4*)(f + k);
        float4 b = *(const float4*)(w + k);
        sum += a.x * b.x + a.y * b.y + a.z * b.z + a.w * b.w;
    }
    logits[idx] = sum;
}

// ---------------- host orchestration -------------------------------------------
extern "C" void kernel_launch(void* const* d_in, const int* in_sizes, int n_in,
                              void* d_out, int out_size) {
    const float* x_user    = (const float*)d_in[0];
    const float* x_item    = (const float*)d_in[1];
    const int*   e_u2i     = (const int*)d_in[2];
    const int*   e_i2u     = (const int*)d_in[3];
    const int*   b_user    = (const int*)d_in[4];
    const int*   b_item    = (const int*)d_in[5];
    const float* Wrel_u2i  = (const float*)d_in[6];
    const float* Wroot_u2i = (const float*)d_in[7];
    const float* b_u2i     = (const float*)d_in[8];
    const float* Wrel_i2u  = (const float*)d_in[9];
    const float* Wroot_i2u = (const float*)d_in[10];
    const float* b_i2u     = (const float*)d_in[11];
    const float* bn_g_user = (const float*)d_in[12];
    const float* bn_b_user = (const float*)d_in[13];
    const float* bn_g_item = (const float*)d_in[14];
    const float* bn_b_item = (const float*)d_in[15];
    const float* fc_W      = (const float*)d_in[16];
    const float* fc_b      = (const float*)d_in[17];

    float* out   = (float*)d_out;
    float* feats = out + NL * NG * NC;

    float *xu, *xi, *newu, *newi, *aggu, *aggi, *stats;
    char* wpre;
    int *rowi, *rowu, *col_u2i, *col_i2u, *degi, *degu, *curi, *curu, *su, *si;
    cudaGetSymbolAddress((void**)&xu, g_xu);
    cudaGetSymbolAddress((void**)&xi, g_xi);
    cudaGetSymbolAddress((void**)&newu, g_newu);
    cudaGetSymbolAddress((void**)&newi, g_newi);
    cudaGetSymbolAddress((void**)&aggu, g_aggu);
    cudaGetSymbolAddress((void**)&aggi, g_aggi);
    cudaGetSymbolAddress((void**)&wpre, g_wpre);
    cudaGetSymbolAddress((void**)&stats, g_stats);
    cudaGetSymbolAddress((void**)&rowi, g_rowi);
    cudaGetSymbolAddress((void**)&rowu, g_rowu);
    cudaGetSymbolAddress((void**)&col_u2i, g_col_u2i);
    cudaGetSymbolAddress((void**)&col_i2u, g_col_i2u);
    cudaGetSymbolAddress((void**)&degi, g_degi);
    cudaGetSymbolAddress((void**)&degu, g_degu);
    cudaGetSymbolAddress((void**)&curi, g_curi);
    cudaGetSymbolAddress((void**)&curu, g_curu);
    cudaGetSymbolAddress((void**)&su, g_su);
    cudaGetSymbolAddress((void**)&si, g_si);

    cudaFuncSetAttribute(k_gemm2, cudaFuncAttributeMaxDynamicSharedMemorySize, GEMM_SMEM);

    const int T = 256;
    const int NBLK = CDIV(N5, 128);

    // setup
    k_init<<<CDIV(N5, T), T>>>(stats, degi, degu, curi, curu);
    k_hist2<<<CDIV(2*NE, T), T>>>(e_u2i + NE, e_i2u + NE, degi, degu);
    k_scan2<<<2, 1024>>>(degi, rowi, degu, rowu);
    k_scatter2<<<CDIV(2*NE, T), T>>>(e_u2i, e_i2u, rowi, curi, col_u2i,
                                     rowu, curu, col_i2u);
    k_offsets2<<<CDIV(2*(NG+1), 128), 128>>>(b_user, b_item, su, si);
    k_prepw<<<CDIV(NL*2*2*128*64, T), T>>>(Wrel_u2i, Wroot_u2i, Wrel_i2u, Wroot_i2u, wpre);

    // ---- layers --------------------------------------------------------------
    const float* prevU = x_user;
    const float* prevI = x_item;
    float* bufsU[NL] = { xu, newu, xu };
    float* bufsI[NL] = { xi, newi, xi };

    for (int l = 0; l < NL; l++) {
        float* curU = bufsU[l];
        float* curI = bufsI[l];
        float* stats_u = stats + (size_t)(l*2 + 0) * 2 * HD;
        float* stats_i = stats + (size_t)(l*2 + 1) * 2 * HD;
        const float* pstats_u = (l > 0) ? stats + (size_t)((l-1)*2 + 0) * 2 * HD : stats;
        const float* pstats_i = (l > 0) ? stats + (size_t)((l-1)*2 + 1) * 2 * HD : stats;

        k_agg2<<<CDIV(2*(NI+NU)*32, T), T>>>(rowi, col_u2i, prevU, aggi,
                                             rowu, col_i2u, prevI, aggu);

        GemmSide SI;
        SI.agg = aggi; SI.xprev = prevI;
        SI.wpre = wpre + ((size_t)l * 2 + 0) * 131072;
        SI.bias = b_u2i + (size_t)l*HD;
        SI.out = curI; SI.statsAcc = stats_i; SI.rowp = rowi;
        SI.statsS = pstats_u; SI.gS = bn_g_user; SI.bS = bn_b_user;
        SI.statsD = pstats_i; SI.gD = bn_g_item; SI.bD = bn_b_item;

        GemmSide SU;
        SU.agg = aggu; SU.xprev = prevU;
        SU.wpre = wpre + ((size_t)l * 2 + 1) * 131072;
        SU.bias = b_i2u + (size_t)l*HD;
        SU.out = curU; SU.statsAcc = stats_u; SU.rowp = rowu;
        SU.statsS = pstats_i; SU.gS = bn_g_item; SU.bS = bn_b_item;
        SU.statsD = pstats_u; SU.gD = bn_g_user; SU.bD = bn_b_user;

        k_gemm2<<<2*NBLK, 256, GEMM_SMEM>>>(SI, SU, NBLK, l > 0 ? 1 : 0);

        k_pool<<<NG, 512>>>(curU, curI, su, si,
                            stats_u, bn_g_user, bn_b_user,
                            stats_i, bn_g_item, bn_b_item,
                            feats + (size_t)l*NG*HD);

        prevU = curU; prevI = curI;
    }

    k_logits<<<CDIV(NL*NG*NC, T), T>>>(feats, fc_W, fc_b, out);
}

// round 13
// speedup vs baseline: 1.0678x; 1.0678x over previous
#include <cuda_runtime.h>
#include <cuda_bf16.h>
#include <cstdint>
#include <math.h>

#define NU 50000
#define NI 50000
#define N5 50000
#define HD 128
#define NE 800000
#define NG 512
#define NC 16
#define NL 3
#define BN_EPS 1e-5f

#define CDIV(a,b) (((a)+(b)-1)/(b))

// ---------------- scratch (static device globals; no runtime alloc) -------------
__device__ float  g_xu[(size_t)NU*HD];
__device__ float  g_xi[(size_t)NI*HD];
__device__ float  g_newu[(size_t)NU*HD];
__device__ float  g_newi[(size_t)NI*HD];
__device__ float  g_aggu[(size_t)NU*HD];
__device__ float  g_aggi[(size_t)NI*HD];
__device__ char   g_wpre[(size_t)NL*2*131072];  // [layer][side][h][hi|lo] 4x32KB
__device__ int    g_rowi[NI+1];
__device__ int    g_rowu[NU+1];
__device__ int    g_col_u2i[NE];
__device__ int    g_col_i2u[NE];
__device__ int    g_degi[NI];
__device__ int    g_degu[NU];
__device__ int    g_curi[NI];
__device__ int    g_curu[NU];
__device__ float  g_stats[NL*2*2*HD];
__device__ int    g_su[NG+1];
__device__ int    g_si[NG+1];

// =================== helpers ====================================================
__device__ __forceinline__ uint32_t smem_u32(const void* p) {
    uint32_t a;
    asm("{ .reg .u64 t; cvta.to.shared.u64 t, %1; cvt.u32.u64 %0, t; }" : "=r"(a) : "l"(p));
    return a;
}
__device__ __forceinline__ void ldsm4(uint32_t* r, uint32_t addr) {
    asm volatile("ldmatrix.sync.aligned.m8n8.x4.shared.b16 {%0,%1,%2,%3}, [%4];"
        : "=r"(r[0]), "=r"(r[1]), "=r"(r[2]), "=r"(r[3]) : "r"(addr));
}
__device__ __forceinline__ void mma16816(float* d, const uint32_t* a, const uint32_t* b) {
    asm volatile(
        "mma.sync.aligned.m16n8k16.row.col.f32.bf16.bf16.f32 "
        "{%0,%1,%2,%3}, {%4,%5,%6,%7}, {%8,%9}, {%0,%1,%2,%3};"
        : "+f"(d[0]), "+f"(d[1]), "+f"(d[2]), "+f"(d[3])
        : "r"(a[0]), "r"(a[1]), "r"(a[2]), "r"(a[3]), "r"(b[0]), "r"(b[1]));
}
__device__ __forceinline__ void split2(float a, float b, uint32_t& hi, uint32_t& lo) {
    __nv_bfloat16 ah = __float2bfloat16(a);
    __nv_bfloat16 bh = __float2bfloat16(b);
    __nv_bfloat16 al = __float2bfloat16(a - __bfloat162float(ah));
    __nv_bfloat16 bl = __float2bfloat16(b - __bfloat162float(bh));
    hi = (uint32_t)__bfloat16_as_ushort(ah) | ((uint32_t)__bfloat16_as_ushort(bh) << 16);
    lo = (uint32_t)__bfloat16_as_ushort(al) | ((uint32_t)__bfloat16_as_ushort(bl) << 16);
}

// ---------------- merged setup kernels ------------------------------------------
__global__ void k_init(float* stats, int* degi, int* degu) {
    int i = blockIdx.x * blockDim.x + threadIdx.x;
    if (i < NL*2*2*HD) stats[i] = 0.f;
    if (i < NI) degi[i] = 0;
    if (i < NU) degu[i] = 0;
}
__global__ void k_hist2(const int* __restrict__ dsti, const int* __restrict__ dstu,
                        int* __restrict__ degi, int* __restrict__ degu) {
    int e = blockIdx.x * blockDim.x + threadIdx.x;
    if (e < NE) atomicAdd(&degi[dsti[e]], 1);
    else if (e < 2*NE) atomicAdd(&degu[dstu[e - NE]], 1);
}
// scan also seeds cur[i] = row[i] so scatter needs no rowp read
__device__ void scan_one(const int* __restrict__ deg, int n, int* __restrict__ row,
                         int* __restrict__ cur) {
    __shared__ int part[1024];
    int t = threadIdx.x;
    int chunk = (n + 1023) / 1024;
    int s0 = t * chunk, s1 = min(s0 + chunk, n);
    int sum = 0;
    for (int i = s0; i < s1; i++) sum += deg[i];
    part[t] = sum;
    __syncthreads();
    for (int d = 1; d < 1024; d <<= 1) {
        int v = 0;
        if (t >= d) v = part[t - d];
        __syncthreads();
        if (t >= d) part[t] += v;
        __syncthreads();
    }
    int excl = (t == 0) ? 0 : part[t - 1];
    for (int i = s0; i < s1; i++) { row[i] = excl; cur[i] = excl; excl += deg[i]; }
    if (t == 1023) row[n] = excl;
}
__global__ void k_scan2(const int* __restrict__ degi, int* __restrict__ rowi, int* __restrict__ curi,
                        const int* __restrict__ degu, int* __restrict__ rowu, int* __restrict__ curu) {
    if (blockIdx.x == 0) scan_one(degi, NI, rowi, curi);
    else                 scan_one(degu, NU, rowu, curu);
}
__global__ void k_scatter2(const int* __restrict__ ei, const int* __restrict__ eu,
                           int* __restrict__ curi, int* __restrict__ coli,
                           int* __restrict__ curu, int* __restrict__ colu) {
    int e = blockIdx.x * blockDim.x + threadIdx.x;
    if (e < NE) {
        int d = ei[NE + e];
        int p = atomicAdd(&curi[d], 1);
        coli[p] = ei[e];
    } else if (e < 2*NE) {
        int ee = e - NE;
        int d = eu[NE + ee];
        int p = atomicAdd(&curu[d], 1);
        colu[p] = eu[ee];
    }
}
__global__ void k_offsets2(const int* __restrict__ bu, const int* __restrict__ bi,
                           int* __restrict__ su, int* __restrict__ si) {
    int i = blockIdx.x * blockDim.x + threadIdx.x;
    int g = (i <= NG) ? i : i - (NG + 1);
    if (g > NG || i > 2*NG + 1) return;
    const int* batch = (i <= NG) ? bu : bi;
    int* off = (i <= NG) ? su : si;
    int lo = 0, hi = N5;
    while (lo < hi) { int mid = (lo + hi) >> 1; if (batch[mid] < g) lo = mid + 1; else hi = mid; }
    off[g] = lo;
}

// ---------------- weight preconversion into the gemm's swizzled smem layout -----
__global__ void k_prepw(const float* __restrict__ Wrel_u2i, const float* __restrict__ Wroot_u2i,
                        const float* __restrict__ Wrel_i2u, const float* __restrict__ Wroot_i2u,
                        char* __restrict__ wpre) {
    int idx = blockIdx.x * blockDim.x + threadIdx.x;
    if (idx >= NL * 2 * 2 * 128 * 64) return;       // (l, side, h, n, pair)
    int pair = idx & 63;
    int n    = (idx >> 6) & 127;
    int h    = (idx >> 13) & 1;
    int side = (idx >> 14) & 1;
    int l    = idx >> 15;
    const float* W = (side == 0) ? (h ? Wroot_u2i : Wrel_u2i)
                                 : (h ? Wroot_i2u : Wrel_i2u);
    W += (size_t)l * HD * HD + (size_t)n * HD + pair * 2;
    uint32_t hi, lo;
    split2(W[0], W[1], hi, lo);
    int k = pair * 2;
    int c = k >> 3;
    int off = n * 256 + ((c ^ (n & 7)) << 4) + (k & 7) * 2;
    size_t base = ((size_t)l * 2 + side) * 131072;
    *(uint32_t*)(wpre + base + (size_t)(h * 2 + 0) * 32768 + off) = hi;
    *(uint32_t*)(wpre + base + (size_t)(h * 2 + 1) * 32768 + off) = lo;
}

// ---------------- aggregation: warp per destination node (R11 form) -------------
__device__ __forceinline__ void agg_one(const int* __restrict__ rowp,
                                        const int* __restrict__ col,
                                        const float* __restrict__ src,
                                        float* __restrict__ dst, int node, int lane) {
    int s = rowp[node], e = rowp[node + 1];
    float4 acc = make_float4(0.f, 0.f, 0.f, 0.f);
    for (int j = s; j < e; j += 32) {
        int m = min(32, e - j);
        int idx = (lane < m) ? col[j + lane] : 0;
        for (int t = 0; t < m; t++) {
            int sidx = __shfl_sync(0xffffffffu, idx, t);
            float4 v = ((const float4*)(src + (size_t)sidx * HD))[lane];
            acc.x += v.x; acc.y += v.y; acc.z += v.z; acc.w += v.w;
        }
    }
    ((float4*)(dst + (size_t)node * HD))[lane] = acc;
}

__global__ void k_agg2(const int* __restrict__ rowi, const int* __restrict__ coli,
                       const float* __restrict__ srcU, float* __restrict__ dstI,
                       const int* __restrict__ rowu, const int* __restrict__ colu,
                       const float* __restrict__ srcI, float* __restrict__ dstU) {
    int w = (blockIdx.x * blockDim.x + threadIdx.x) >> 5;
    int lane = threadIdx.x & 31;
    if (w < NI)            agg_one(rowi, coli, srcU, dstI, w, lane);
    else if (w < NI + NU)  agg_one(rowu, colu, srcI, dstU, w - NI, lane);
}

// ============== mma.sync GEMM (R5 structure), preconverted weights ==============
#define A_HI 0
#define A_LO 32768
#define B_HI 65536
#define B_LO 98304
#define SMF_STRIDE 136
#define SSUM_OFF 100352
#define SSQ_OFF  100864
#define AFF_OFF  131072
#define GEMM_SMEM (131072 + 2560)

struct GemmSide {
    const float* agg;
    const float* xprev;
    const char*  wpre;
    const float* bias;
    float*       out;
    float*       statsAcc;
    const int*   rowp;
    const float* statsS;  const float* gS; const float* bS;
    const float* statsD;  const float* gD; const float* bD;
};

__global__ __launch_bounds__(256, 1)
void k_gemm2(GemmSide SI, GemmSide SU, int nblk0, int use_affine)
{
    extern __shared__ __align__(128) char smem[];
    uint32_t sb = smem_u32(smem);
    int tid = threadIdx.x;
    int lane = tid & 31, warp = tid >> 5;
    int warpM = warp & 3, warpN = warp >> 2;

    const GemmSide& S = (blockIdx.x < nblk0) ? SI : SU;
    int row0 = ((blockIdx.x < nblk0) ? blockIdx.x : blockIdx.x - nblk0) * 128;

    float* affSa = (float*)(smem + AFF_OFF);
    float* affSb = affSa + 128;
    float* affDa = affSb + 128;
    float* affDb = affDa + 128;
    float* degf  = affDb + 128;
    if (tid < 128) {
        float sa0 = 1.f, sb0 = 0.f, sa1 = 1.f, sb1 = 0.f;
        if (use_affine) {
            const float invN = 1.f / (float)N5;
            float m = S.statsS[tid] * invN;
            float var = S.statsS[HD + tid] * invN - m * m;
            float a = S.gS[tid] * rsqrtf(fmaxf(var, 0.f) + BN_EPS);
            sa0 = a; sb0 = S.bS[tid] - m * a;
            m = S.statsD[tid] * invN;
            var = S.statsD[HD + tid] * invN - m * m;
            a = S.gD[tid] * rsqrtf(fmaxf(var, 0.f) + BN_EPS);
            sa1 = a; sb1 = S.bD[tid] - m * a;
        }
        affSa[tid] = sa0; affSb[tid] = sb0; affDa[tid] = sa1; affDb[tid] = sb1;
    } else {
        int r = tid - 128;
        int gr = row0 + r;
        degf[r] = (gr < N5) ? (float)(S.rowp[gr + 1] - S.rowp[gr]) : 0.f;
    }
    __syncthreads();

    int mi = lane >> 3;
    int lr = lane & 7;
    int a_kmi = mi >> 1;
    uint32_t a_off[2], a_xor[2];
#pragma unroll
    for (int mt = 0; mt < 2; mt++) {
        int r = warpM * 32 + mt * 16 + (mi & 1) * 8 + lr;
        a_off[mt] = r * 256;
        a_xor[mt] = r & 7;
    }
    int b_kmi = mi & 1;
    uint32_t b_off[4], b_xor[4];
#pragma unroll
    for (int jj = 0; jj < 4; jj++) {
        int r = warpN * 64 + jj * 16 + (mi >> 1) * 8 + lr;
        b_off[jj] = r * 256;
        b_xor[jj] = r & 7;
    }

    float acc[2][8][4];
#pragma unroll
    for (int mt = 0; mt < 2; mt++)
#pragma unroll
        for (int j = 0; j < 8; j++)
#pragma unroll
            for (int t = 0; t < 4; t++) acc[mt][j][t] = 0.f;

    for (int h = 0; h < 2; h++) {
        if (h) __syncthreads();
        const float* As = h ? S.xprev : S.agg;
        const float* ka = h ? affDa : affSa;
        const float* kb = h ? affDb : affSb;
        // fill A tile: affine + bf16 hi/lo split, chunk-swizzled
#pragma unroll
        for (int i = 0; i < 8; i++) {
            int lin = tid + i * 256;
            int r = lin >> 4, c = lin & 15;
            int gr = row0 + r;
            float ds = h ? 1.f : degf[r];
            float4 v0 = make_float4(0.f,0.f,0.f,0.f), v1 = v0;
            if (gr < N5) {
                v0 = *(const float4*)(As + (size_t)gr * HD + c * 8);
                v1 = *(const float4*)(As + (size_t)gr * HD + c * 8 + 4);
            }
            float4 ka0 = *(const float4*)&ka[c * 8];
            float4 ka1 = *(const float4*)&ka[c * 8 + 4];
            float4 kb0 = *(const float4*)&kb[c * 8];
            float4 kb1 = *(const float4*)&kb[c * 8 + 4];
            v0.x = ka0.x * v0.x + ds * kb0.x;
            v0.y = ka0.y * v0.y + ds * kb0.y;
            v0.z = ka0.z * v0.z + ds * kb0.z;
            v0.w = ka0.w * v0.w + ds * kb0.w;
            v1.x = ka1.x * v1.x + ds * kb1.x;
            v1.y = ka1.y * v1.y + ds * kb1.y;
            v1.z = ka1.z * v1.z + ds * kb1.z;
            v1.w = ka1.w * v1.w + ds * kb1.w;
            uint32_t h0,l0,h1,l1,h2,l2,h3,l3;
            split2(v0.x, v0.y, h0, l0); split2(v0.z, v0.w, h1, l1);
            split2(v1.x, v1.y, h2, l2); split2(v1.z, v1.w, h3, l3);
            int off = r * 256 + ((c ^ (r & 7)) << 4);
            *(uint4*)(smem + A_HI + off) = make_uint4(h0, h1, h2, h3);
            *(uint4*)(smem + A_LO + off) = make_uint4(l0, l1, l2, l3);
        }
        // fill B tile: straight uint4 copy of preconverted blocks
        {
            const uint4* srcH = (const uint4*)(S.wpre + (size_t)(h * 2 + 0) * 32768);
            const uint4* srcL = (const uint4*)(S.wpre + (size_t)(h * 2 + 1) * 32768);
            uint4* dH = (uint4*)(smem + B_HI);
            uint4* dL = (uint4*)(smem + B_LO);
#pragma unroll
            for (int i = 0; i < 8; i++) {
                dH[tid + i * 256] = srcH[tid + i * 256];
                dL[tid + i * 256] = srcL[tid + i * 256];
            }
        }
        __syncthreads();

#pragma unroll
        for (int p = 0; p < 3; p++) {
            uint32_t bA = sb + ((p == 1) ? A_LO : A_HI);
            uint32_t bB = sb + ((p == 2) ? B_LO : B_HI);
#pragma unroll
            for (int ks = 0; ks < 8; ks++) {
                uint32_t afr[2][4];
#pragma unroll
                for (int mt = 0; mt < 2; mt++) {
                    uint32_t ck = (uint32_t)((ks << 1) | a_kmi) ^ a_xor[mt];
                    ldsm4(afr[mt], bA + a_off[mt] + (ck << 4));
                }
                uint32_t bfr[8][2];
#pragma unroll
                for (int jj = 0; jj < 4; jj++) {
                    uint32_t q[4];
                    uint32_t ck = (uint32_t)((ks << 1) | b_kmi) ^ b_xor[jj];
                    ldsm4(q, bB + b_off[jj] + (ck << 4));
                    bfr[2*jj][0] = q[0]; bfr[2*jj][1] = q[1];
                    bfr[2*jj+1][0] = q[2]; bfr[2*jj+1][1] = q[3];
                }
#pragma unroll
                for (int mt = 0; mt < 2; mt++)
#pragma unroll
                    for (int j = 0; j < 8; j++)
                        mma16816(acc[mt][j], afr[mt], bfr[j]);
            }
        }
    }
    __syncthreads();

    float* smF = (float*)smem;
    float* ssum = (float*)(smem + SSUM_OFF);
    float* ssq  = (float*)(smem + SSQ_OFF);
    if (tid < 128) { ssum[tid] = 0.f; ssq[tid] = 0.f; }
#pragma unroll
    for (int mt = 0; mt < 2; mt++) {
        int r0 = warpM * 32 + mt * 16 + (lane >> 2);
        int c  = warpN * 64 + (lane & 3) * 2;
#pragma unroll
        for (int j = 0; j < 8; j++) {
            int cc = c + j * 8;
            *(float2*)&smF[r0 * SMF_STRIDE + cc]       = make_float2(acc[mt][j][0], acc[mt][j][1]);
            *(float2*)&smF[(r0 + 8) * SMF_STRIDE + cc] = make_float2(acc[mt][j][2], acc[mt][j][3]);
        }
    }
    __syncthreads();

    // bias + relu + store + BN stats
    {
        int c4 = tid & 31, rg = tid >> 5;
        float4 bv = *(const float4*)(S.bias + c4 * 4);
        float s0=0,s1=0,s2=0,s3=0,q0=0,q1=0,q2=0,q3=0;
#pragma unroll
        for (int it = 0; it < 16; it++) {
            int r = it * 8 + rg;
            int gr = row0 + r;
            if (gr < N5) {
                float4 v = *(float4*)&smF[r * SMF_STRIDE + c4 * 4];
                v.x = fmaxf(v.x + bv.x, 0.f);
                v.y = fmaxf(v.y + bv.y, 0.f);
                v.z = fmaxf(v.z + bv.z, 0.f);
                v.w = fmaxf(v.w + bv.w, 0.f);
                *(float4*)(S.out + (size_t)gr * HD + c4 * 4) = v;
                s0 += v.x; s1 += v.y; s2 += v.z; s3 += v.w;
                q0 += v.x*v.x; q1 += v.y*v.y; q2 += v.z*v.z; q3 += v.w*v.w;
            }
        }
        atomicAdd(&ssum[c4*4+0], s0); atomicAdd(&ssum[c4*4+1], s1);
        atomicAdd(&ssum[c4*4+2], s2); atomicAdd(&ssum[c4*4+3], s3);
        atomicAdd(&ssq[c4*4+0], q0);  atomicAdd(&ssq[c4*4+1], q1);
        atomicAdd(&ssq[c4*4+2], q2);  atomicAdd(&ssq[c4*4+3], q3);
    }
    __syncthreads();
    if (tid < 128) {
        atomicAdd(&S.statsAcc[tid], ssum[tid]);
        atomicAdd(&S.statsAcc[HD + tid], ssq[tid]);
    }
}

// ---------------- pooling: 512 threads, 4-way row split + smem reduce -----------
__global__ __launch_bounds__(512)
void k_pool(const float* __restrict__ xu, const float* __restrict__ xi,
            const int* __restrict__ su, const int* __restrict__ si,
            const float* __restrict__ statsU, const float* __restrict__ gU,
            const float* __restrict__ btU,
            const float* __restrict__ statsI, const float* __restrict__ gI,
            const float* __restrict__ btI,
            float* __restrict__ feats) {
    __shared__ float red[512];
    int g = blockIdx.x;
    int tid = threadIdx.x;
    int c = tid & 127;
    int chunk = tid >> 7;       // 0..3

    int u0 = su[g], u1 = su[g + 1];
    int i0 = si[g], i1 = si[g + 1];
    float sumU = 0.f, sumI = 0.f;
    for (int r = u0 + chunk; r < u1; r += 4) sumU += xu[(size_t)r * HD + c];
    for (int r = i0 + chunk; r < i1; r += 4) sumI += xi[(size_t)r * HD + c];
    red[tid] = sumU;
    __syncthreads();
    if (chunk == 0) sumU = red[c] + red[128 + c] + red[256 + c] + red[384 + c];
    __syncthreads();
    red[tid] = sumI;
    __syncthreads();
    if (chunk == 0) {
        sumI = red[c] + red[128 + c] + red[256 + c] + red[384 + c];
        const float invN = 1.f / (float)N5;
        float mU = statsU[c] * invN;
        float vU = statsU[HD + c] * invN - mU * mU;
        float aU = gU[c] * rsqrtf(fmaxf(vU, 0.f) + BN_EPS);
        float bU = btU[c] - mU * aU;
        float mI = statsI[c] * invN;
        float vI = statsI[HD + c] * invN - mI * mI;
        float aI = gI[c] * rsqrtf(fmaxf(vI, 0.f) + BN_EPS);
        float bI = btI[c] - mI * aI;
        float nu = (float)(u1 - u0), ni = (float)(i1 - i0);
        float cnt = fmaxf(nu + ni, 1.f);
        feats[(size_t)g * HD + c] = (aU * sumU + nu * bU + aI * sumI + ni * bI) / cnt;
    }
}

// ---------------- per-layer classifier heads ------------------------------------
__global__ void k_logits(const float* __restrict__ feats, const float* __restrict__ fcW,
                         const float* __restrict__ fcb, float* __restrict__ logits) {
    int idx = blockIdx.x * blockDim.x + threadIdx.x;
    if (idx >= NL * NG * NC) return;
    int l = idx / (NG * NC);
    int g = (idx / NC) % NG;
    int c = idx % NC;
    const float* f = feats + ((size_t)l * NG + g) * HD;
    const float* w = fcW + ((size_t)l * NC + c) * HD;
    float sum = fcb[l * NC + c];
#pragma unroll
    for (int k = 0; k < HD; k += 4) {
        float4 a = *(const float4*)(f + k);
        float4 b = *(const float4*)(w + k);
        sum += a.x * b.x + a.y * b.y + a.z * b.z + a.w * b.w;
    }
    logits[idx] = sum;
}

// ---------------- host orchestration -------------------------------------------
extern "C" void kernel_launch(void* const* d_in, const int* in_sizes, int n_in,
                              void* d_out, int out_size) {
    const float* x_user    = (const float*)d_in[0];
    const float* x_item    = (const float*)d_in[1];
    const int*   e_u2i     = (const int*)d_in[2];
    const int*   e_i2u     = (const int*)d_in[3];
    const int*   b_user    = (const int*)d_in[4];
    const int*   b_item    = (const int*)d_in[5];
    const float* Wrel_u2i  = (const float*)d_in[6];
    const float* Wroot_u2i = (const float*)d_in[7];
    const float* b_u2i     = (const float*)d_in[8];
    const float* Wrel_i2u  = (const float*)d_in[9];
    const float* Wroot_i2u = (const float*)d_in[10];
    const float* b_i2u     = (const float*)d_in[11];
    const float* bn_g_user = (const float*)d_in[12];
    const float* bn_b_user = (const float*)d_in[13];
    const float* bn_g_item = (const float*)d_in[14];
    const float* bn_b_item = (const float*)d_in[15];
    const float* fc_W      = (const float*)d_in[16];
    const float* fc_b      = (const float*)d_in[17];

    float* out   = (float*)d_out;
    float* feats = out + NL * NG * NC;

    float *xu, *xi, *newu, *newi, *aggu, *aggi, *stats;
    char* wpre;
    int *rowi, *rowu, *col_u2i, *col_i2u, *degi, *degu, *curi, *curu, *su, *si;
    cudaGetSymbolAddress((void**)&xu, g_xu);
    cudaGetSymbolAddress((void**)&xi, g_xi);
    cudaGetSymbolAddress((void**)&newu, g_newu);
    cudaGetSymbolAddress((void**)&newi, g_newi);
    cudaGetSymbolAddress((void**)&aggu, g_aggu);
    cudaGetSymbolAddress((void**)&aggi, g_aggi);
    cudaGetSymbolAddress((void**)&wpre, g_wpre);
    cudaGetSymbolAddress((void**)&stats, g_stats);
    cudaGetSymbolAddress((void**)&rowi, g_rowi);
    cudaGetSymbolAddress((void**)&rowu, g_rowu);
    cudaGetSymbolAddress((void**)&col_u2i, g_col_u2i);
    cudaGetSymbolAddress((void**)&col_i2u, g_col_i2u);
    cudaGetSymbolAddress((void**)&degi, g_degi);
    cudaGetSymbolAddress((void**)&degu, g_degu);
    cudaGetSymbolAddress((void**)&curi, g_curi);
    cudaGetSymbolAddress((void**)&curu, g_curu);
    cudaGetSymbolAddress((void**)&su, g_su);
    cudaGetSymbolAddress((void**)&si, g_si);

    cudaFuncSetAttribute(k_gemm2, cudaFuncAttributeMaxDynamicSharedMemorySize, GEMM_SMEM);

    const int T = 256;
    const int NBLK = CDIV(N5, 128);

    // setup
    k_init<<<CDIV(N5, T), T>>>(stats, degi, degu);
    k_hist2<<<CDIV(2*NE, T), T>>>(e_u2i + NE, e_i2u + NE, degi, degu);
    k_scan2<<<2, 1024>>>(degi, rowi, curi, degu, rowu, curu);
    k_scatter2<<<CDIV(2*NE, T), T>>>(e_u2i, e_i2u, curi, col_u2i, curu, col_i2u);
    k_offsets2<<<CDIV(2*(NG+1), 128), 128>>>(b_user, b_item, su, si);
    k_prepw<<<CDIV(NL*2*2*128*64, T), T>>>(Wrel_u2i, Wroot_u2i, Wrel_i2u, Wroot_i2u, wpre);

    // ---- layers --------------------------------------------------------------
    const float* prevU = x_user;
    const float* prevI = x_item;
    float* bufsU[NL] = { xu, newu, xu };
    float* bufsI[NL] = { xi, newi, xi };

    for (int l = 0; l < NL; l++) {
        float* curU = bufsU[l];
        float* curI = bufsI[l];
        float* stats_u = stats + (size_t)(l*2 + 0) * 2 * HD;
        float* stats_i = stats + (size_t)(l*2 + 1) * 2 * HD;
        const float* pstats_u = (l > 0) ? stats + (size_t)((l-1)*2 + 0) * 2 * HD : stats;
        const float* pstats_i = (l > 0) ? stats + (size_t)((l-1)*2 + 1) * 2 * HD : stats;

        k_agg2<<<CDIV((NI+NU)*32, T), T>>>(rowi, col_u2i, prevU, aggi,
                                           rowu, col_i2u, prevI, aggu);

        GemmSide SI;
        SI.agg = aggi; SI.xprev = prevI;
        SI.wpre = wpre + ((size_t)l * 2 + 0) * 131072;
        SI.bias = b_u2i + (size_t)l*HD;
        SI.out = curI; SI.statsAcc = stats_i; SI.rowp = rowi;
        SI.statsS = pstats_u; SI.gS = bn_g_user; SI.bS = bn_b_user;
        SI.statsD = pstats_i; SI.gD = bn_g_item; SI.bD = bn_b_item;

        GemmSide SU;
        SU.agg = aggu; SU.xprev = prevU;
        SU.wpre = wpre + ((size_t)l * 2 + 1) * 131072;
        SU.bias = b_i2u + (size_t)l*HD;
        SU.out = curU; SU.statsAcc = stats_u; SU.rowp = rowu;
        SU.statsS = pstats_i; SU.gS = bn_g_item; SU.bS = bn_b_item;
        SU.statsD = pstats_u; SU.gD = bn_g_user; SU.bD = bn_b_user;

        k_gemm2<<<2*NBLK, 256, GEMM_SMEM>>>(SI, SU, NBLK, l > 0 ? 1 : 0);

        k_pool<<<NG, 512>>>(curU, curI, su, si,
                            stats_u, bn_g_user, bn_b_user,
                            stats_i, bn_g_item, bn_b_item,
                            feats + (size_t)l*NG*HD);

        prevU = curU; prevI = curI;
    }

    k_logits<<<CDIV(NL*NG*NC, T), T>>>(feats, fc_W, fc_b, out);
}

// round 14
// speedup vs baseline: 1.1164x; 1.0455x over previous
#include <cuda_runtime.h>
#include <cuda_bf16.h>
#include <cstdint>
#include <math.h>

#define NU 50000
#define NI 50000
#define N5 50000
#define HD 128
#define NE 800000
#define NG 512
#define NC 16
#define NL 3
#define BN_EPS 1e-5f

#define CDIV(a,b) (((a)+(b)-1)/(b))

// ---------------- scratch (static device globals; no runtime alloc) -------------
__device__ float  g_xu[(size_t)NU*HD];
__device__ float  g_xi[(size_t)NI*HD];
__device__ float  g_newu[(size_t)NU*HD];
__device__ float  g_newi[(size_t)NI*HD];
__device__ float  g_aggu[(size_t)NU*HD];
__device__ float  g_aggi[(size_t)NI*HD];
__device__ char   g_wpre[(size_t)NL*2*131072];  // [layer][side][h][hi|lo] 4x32KB
__device__ int    g_rowi[NI+1];
__device__ int    g_rowu[NU+1];
__device__ int    g_col_u2i[NE];
__device__ int    g_col_i2u[NE];
__device__ int    g_degi[NI];
__device__ int    g_degu[NU];
__device__ int    g_curi[NI];
__device__ int    g_curu[NU];
__device__ float  g_stats[NL*2*2*HD];
__device__ int    g_su[NG+1];
__device__ int    g_si[NG+1];

// =================== helpers ====================================================
__device__ __forceinline__ uint32_t smem_u32(const void* p) {
    uint32_t a;
    asm("{ .reg .u64 t; cvta.to.shared.u64 t, %1; cvt.u32.u64 %0, t; }" : "=r"(a) : "l"(p));
    return a;
}
__device__ __forceinline__ void ldsm4(uint32_t* r, uint32_t addr) {
    asm volatile("ldmatrix.sync.aligned.m8n8.x4.shared.b16 {%0,%1,%2,%3}, [%4];"
        : "=r"(r[0]), "=r"(r[1]), "=r"(r[2]), "=r"(r[3]) : "r"(addr));
}
__device__ __forceinline__ void mma16816(float* d, const uint32_t* a, const uint32_t* b) {
    asm volatile(
        "mma.sync.aligned.m16n8k16.row.col.f32.bf16.bf16.f32 "
        "{%0,%1,%2,%3}, {%4,%5,%6,%7}, {%8,%9}, {%0,%1,%2,%3};"
        : "+f"(d[0]), "+f"(d[1]), "+f"(d[2]), "+f"(d[3])
        : "r"(a[0]), "r"(a[1]), "r"(a[2]), "r"(a[3]), "r"(b[0]), "r"(b[1]));
}
__device__ __forceinline__ void split2(float a, float b, uint32_t& hi, uint32_t& lo) {
    __nv_bfloat16 ah = __float2bfloat16(a);
    __nv_bfloat16 bh = __float2bfloat16(b);
    __nv_bfloat16 al = __float2bfloat16(a - __bfloat162float(ah));
    __nv_bfloat16 bl = __float2bfloat16(b - __bfloat162float(bh));
    hi = (uint32_t)__bfloat16_as_ushort(ah) | ((uint32_t)__bfloat16_as_ushort(bh) << 16);
    lo = (uint32_t)__bfloat16_as_ushort(al) | ((uint32_t)__bfloat16_as_ushort(bl) << 16);
}

// ---------------- merged setup kernels ------------------------------------------
__global__ void k_init(float* stats, int* degi, int* degu) {
    int i = blockIdx.x * blockDim.x + threadIdx.x;
    if (i < NL*2*2*HD) stats[i] = 0.f;
    if (i < NI) degi[i] = 0;
    if (i < NU) degu[i] = 0;
}
__global__ void k_hist2(const int* __restrict__ dsti, const int* __restrict__ dstu,
                        int* __restrict__ degi, int* __restrict__ degu) {
    int e = blockIdx.x * blockDim.x + threadIdx.x;
    if (e < NE) atomicAdd(&degi[dsti[e]], 1);
    else if (e < 2*NE) atomicAdd(&degu[dstu[e - NE]], 1);
}
// scan also seeds cur[i] = row[i] so scatter needs no rowp read
__device__ void scan_one(const int* __restrict__ deg, int n, int* __restrict__ row,
                         int* __restrict__ cur) {
    __shared__ int part[1024];
    int t = threadIdx.x;
    int chunk = (n + 1023) / 1024;
    int s0 = t * chunk, s1 = min(s0 + chunk, n);
    int sum = 0;
    for (int i = s0; i < s1; i++) sum += deg[i];
    part[t] = sum;
    __syncthreads();
    for (int d = 1; d < 1024; d <<= 1) {
        int v = 0;
        if (t >= d) v = part[t - d];
        __syncthreads();
        if (t >= d) part[t] += v;
        __syncthreads();
    }
    int excl = (t == 0) ? 0 : part[t - 1];
    for (int i = s0; i < s1; i++) { row[i] = excl; cur[i] = excl; excl += deg[i]; }
    if (t == 1023) row[n] = excl;
}
__global__ void k_scan2(const int* __restrict__ degi, int* __restrict__ rowi, int* __restrict__ curi,
                        const int* __restrict__ degu, int* __restrict__ rowu, int* __restrict__ curu) {
    if (blockIdx.x == 0) scan_one(degi, NI, rowi, curi);
    else                 scan_one(degu, NU, rowu, curu);
}
__global__ void k_scatter2(const int* __restrict__ ei, const int* __restrict__ eu,
                           int* __restrict__ curi, int* __restrict__ coli,
                           int* __restrict__ curu, int* __restrict__ colu) {
    int e = blockIdx.x * blockDim.x + threadIdx.x;
    if (e < NE) {
        int d = ei[NE + e];
        int p = atomicAdd(&curi[d], 1);
        coli[p] = ei[e];
    } else if (e < 2*NE) {
        int ee = e - NE;
        int d = eu[NE + ee];
        int p = atomicAdd(&curu[d], 1);
        colu[p] = eu[ee];
    }
}
__global__ void k_offsets2(const int* __restrict__ bu, const int* __restrict__ bi,
                           int* __restrict__ su, int* __restrict__ si) {
    int i = blockIdx.x * blockDim.x + threadIdx.x;
    int g = (i <= NG) ? i : i - (NG + 1);
    if (g > NG || i > 2*NG + 1) return;
    const int* batch = (i <= NG) ? bu : bi;
    int* off = (i <= NG) ? su : si;
    int lo = 0, hi = N5;
    while (lo < hi) { int mid = (lo + hi) >> 1; if (batch[mid] < g) lo = mid + 1; else hi = mid; }
    off[g] = lo;
}

// ---------------- weight preconversion into the gemm's swizzled smem layout -----
__global__ void k_prepw(const float* __restrict__ Wrel_u2i, const float* __restrict__ Wroot_u2i,
                        const float* __restrict__ Wrel_i2u, const float* __restrict__ Wroot_i2u,
                        char* __restrict__ wpre) {
    int idx = blockIdx.x * blockDim.x + threadIdx.x;
    if (idx >= NL * 2 * 2 * 128 * 64) return;       // (l, side, h, n, pair)
    int pair = idx & 63;
    int n    = (idx >> 6) & 127;
    int h    = (idx >> 13) & 1;
    int side = (idx >> 14) & 1;
    int l    = idx >> 15;
    const float* W = (side == 0) ? (h ? Wroot_u2i : Wrel_u2i)
                                 : (h ? Wroot_i2u : Wrel_i2u);
    W += (size_t)l * HD * HD + (size_t)n * HD + pair * 2;
    uint32_t hi, lo;
    split2(W[0], W[1], hi, lo);
    int k = pair * 2;
    int c = k >> 3;
    int off = n * 256 + ((c ^ (n & 7)) << 4) + (k & 7) * 2;
    size_t base = ((size_t)l * 2 + side) * 131072;
    *(uint32_t*)(wpre + base + (size_t)(h * 2 + 0) * 32768 + off) = hi;
    *(uint32_t*)(wpre + base + (size_t)(h * 2 + 1) * 32768 + off) = lo;
}

// ---------------- aggregation: warp/node, uniform col load (no SHFL) ------------
__device__ __forceinline__ void agg_one(const int* __restrict__ rowp,
                                        const int* __restrict__ col,
                                        const float* __restrict__ src,
                                        float* __restrict__ dst, int node, int lane) {
    int s = rowp[node], e = rowp[node + 1];
    float4 acc = make_float4(0.f, 0.f, 0.f, 0.f);
    for (int j = s; j < e; j++) {
        int sidx = __ldg(&col[j]);          // warp-uniform load, L1 broadcast
        float4 v = ((const float4*)(src + (size_t)sidx * HD))[lane];
        acc.x += v.x; acc.y += v.y; acc.z += v.z; acc.w += v.w;
    }
    ((float4*)(dst + (size_t)node * HD))[lane] = acc;
}

__global__ void k_agg2(const int* __restrict__ rowi, const int* __restrict__ coli,
                       const float* __restrict__ srcU, float* __restrict__ dstI,
                       const int* __restrict__ rowu, const int* __restrict__ colu,
                       const float* __restrict__ srcI, float* __restrict__ dstU) {
    int w = (blockIdx.x * blockDim.x + threadIdx.x) >> 5;
    int lane = threadIdx.x & 31;
    if (w < NI)            agg_one(rowi, coli, srcU, dstI, w, lane);
    else if (w < NI + NU)  agg_one(rowu, colu, srcI, dstU, w - NI, lane);
}

// ============== mma.sync GEMM (R5 structure), preconverted weights ==============
#define A_HI 0
#define A_LO 32768
#define B_HI 65536
#define B_LO 98304
#define SMF_STRIDE 136
#define SSUM_OFF 100352
#define SSQ_OFF  100864
#define AFF_OFF  131072
#define GEMM_SMEM (131072 + 2560)

struct GemmSide {
    const float* agg;
    const float* xprev;
    const char*  wpre;
    const float* bias;
    float*       out;
    float*       statsAcc;
    const int*   rowp;
    const float* statsS;  const float* gS; const float* bS;
    const float* statsD;  const float* gD; const float* bD;
};

__global__ __launch_bounds__(256, 1)
void k_gemm2(GemmSide SI, GemmSide SU, int nblk0, int use_affine)
{
    extern __shared__ __align__(128) char smem[];
    uint32_t sb = smem_u32(smem);
    int tid = threadIdx.x;
    int lane = tid & 31, warp = tid >> 5;
    int warpM = warp & 3, warpN = warp >> 2;

    const GemmSide& S = (blockIdx.x < nblk0) ? SI : SU;
    int row0 = ((blockIdx.x < nblk0) ? blockIdx.x : blockIdx.x - nblk0) * 128;

    float* affSa = (float*)(smem + AFF_OFF);
    float* affSb = affSa + 128;
    float* affDa = affSb + 128;
    float* affDb = affDa + 128;
    float* degf  = affDb + 128;
    if (tid < 128) {
        float sa0 = 1.f, sb0 = 0.f, sa1 = 1.f, sb1 = 0.f;
        if (use_affine) {
            const float invN = 1.f / (float)N5;
            float m = S.statsS[tid] * invN;
            float var = S.statsS[HD + tid] * invN - m * m;
            float a = S.gS[tid] * rsqrtf(fmaxf(var, 0.f) + BN_EPS);
            sa0 = a; sb0 = S.bS[tid] - m * a;
            m = S.statsD[tid] * invN;
            var = S.statsD[HD + tid] * invN - m * m;
            a = S.gD[tid] * rsqrtf(fmaxf(var, 0.f) + BN_EPS);
            sa1 = a; sb1 = S.bD[tid] - m * a;
        }
        affSa[tid] = sa0; affSb[tid] = sb0; affDa[tid] = sa1; affDb[tid] = sb1;
    } else {
        int r = tid - 128;
        int gr = row0 + r;
        degf[r] = (gr < N5) ? (float)(S.rowp[gr + 1] - S.rowp[gr]) : 0.f;
    }
    __syncthreads();

    int mi = lane >> 3;
    int lr = lane & 7;
    int a_kmi = mi >> 1;
    uint32_t a_off[2], a_xor[2];
#pragma unroll
    for (int mt = 0; mt < 2; mt++) {
        int r = warpM * 32 + mt * 16 + (mi & 1) * 8 + lr;
        a_off[mt] = r * 256;
        a_xor[mt] = r & 7;
    }
    int b_kmi = mi & 1;
    uint32_t b_off[4], b_xor[4];
#pragma unroll
    for (int jj = 0; jj < 4; jj++) {
        int r = warpN * 64 + jj * 16 + (mi >> 1) * 8 + lr;
        b_off[jj] = r * 256;
        b_xor[jj] = r & 7;
    }

    float acc[2][8][4];
#pragma unroll
    for (int mt = 0; mt < 2; mt++)
#pragma unroll
        for (int j = 0; j < 8; j++)
#pragma unroll
            for (int t = 0; t < 4; t++) acc[mt][j][t] = 0.f;

    for (int h = 0; h < 2; h++) {
        if (h) __syncthreads();
        const float* As = h ? S.xprev : S.agg;
        const float* ka = h ? affDa : affSa;
        const float* kb = h ? affDb : affSb;
        // fill A tile: affine + bf16 hi/lo split, chunk-swizzled
#pragma unroll
        for (int i = 0; i < 8; i++) {
            int lin = tid + i * 256;
            int r = lin >> 4, c = lin & 15;
            int gr = row0 + r;
            float ds = h ? 1.f : degf[r];
            float4 v0 = make_float4(0.f,0.f,0.f,0.f), v1 = v0;
            if (gr < N5) {
                v0 = *(const float4*)(As + (size_t)gr * HD + c * 8);
                v1 = *(const float4*)(As + (size_t)gr * HD + c * 8 + 4);
            }
            float4 ka0 = *(const float4*)&ka[c * 8];
            float4 ka1 = *(const float4*)&ka[c * 8 + 4];
            float4 kb0 = *(const float4*)&kb[c * 8];
            float4 kb1 = *(const float4*)&kb[c * 8 + 4];
            v0.x = ka0.x * v0.x + ds * kb0.x;
            v0.y = ka0.y * v0.y + ds * kb0.y;
            v0.z = ka0.z * v0.z + ds * kb0.z;
            v0.w = ka0.w * v0.w + ds * kb0.w;
            v1.x = ka1.x * v1.x + ds * kb1.x;
            v1.y = ka1.y * v1.y + ds * kb1.y;
            v1.z = ka1.z * v1.z + ds * kb1.z;
            v1.w = ka1.w * v1.w + ds * kb1.w;
            uint32_t h0,l0,h1,l1,h2,l2,h3,l3;
            split2(v0.x, v0.y, h0, l0); split2(v0.z, v0.w, h1, l1);
            split2(v1.x, v1.y, h2, l2); split2(v1.z, v1.w, h3, l3);
            int off = r * 256 + ((c ^ (r & 7)) << 4);
            *(uint4*)(smem + A_HI + off) = make_uint4(h0, h1, h2, h3);
            *(uint4*)(smem + A_LO + off) = make_uint4(l0, l1, l2, l3);
        }
        // fill B tile: straight uint4 copy of preconverted blocks
        {
            const uint4* srcH = (const uint4*)(S.wpre + (size_t)(h * 2 + 0) * 32768);
            const uint4* srcL = (const uint4*)(S.wpre + (size_t)(h * 2 + 1) * 32768);
            uint4* dH = (uint4*)(smem + B_HI);
            uint4* dL = (uint4*)(smem + B_LO);
#pragma unroll
            for (int i = 0; i < 8; i++) {
                dH[tid + i * 256] = srcH[tid + i * 256];
                dL[tid + i * 256] = srcL[tid + i * 256];
            }
        }
        __syncthreads();

#pragma unroll
        for (int p = 0; p < 3; p++) {
            uint32_t bA = sb + ((p == 1) ? A_LO : A_HI);
            uint32_t bB = sb + ((p == 2) ? B_LO : B_HI);
#pragma unroll
            for (int ks = 0; ks < 8; ks++) {
                uint32_t afr[2][4];
#pragma unroll
                for (int mt = 0; mt < 2; mt++) {
                    uint32_t ck = (uint32_t)((ks << 1) | a_kmi) ^ a_xor[mt];
                    ldsm4(afr[mt], bA + a_off[mt] + (ck << 4));
                }
                uint32_t bfr[8][2];
#pragma unroll
                for (int jj = 0; jj < 4; jj++) {
                    uint32_t q[4];
                    uint32_t ck = (uint32_t)((ks << 1) | b_kmi) ^ b_xor[jj];
                    ldsm4(q, bB + b_off[jj] + (ck << 4));
                    bfr[2*jj][0] = q[0]; bfr[2*jj][1] = q[1];
                    bfr[2*jj+1][0] = q[2]; bfr[2*jj+1][1] = q[3];
                }
#pragma unroll
                for (int mt = 0; mt < 2; mt++)
#pragma unroll
                    for (int j = 0; j < 8; j++)
                        mma16816(acc[mt][j], afr[mt], bfr[j]);
            }
        }
    }
    __syncthreads();

    float* smF = (float*)smem;
    float* ssum = (float*)(smem + SSUM_OFF);
    float* ssq  = (float*)(smem + SSQ_OFF);
    if (tid < 128) { ssum[tid] = 0.f; ssq[tid] = 0.f; }
#pragma unroll
    for (int mt = 0; mt < 2; mt++) {
        int r0 = warpM * 32 + mt * 16 + (lane >> 2);
        int c  = warpN * 64 + (lane & 3) * 2;
#pragma unroll
        for (int j = 0; j < 8; j++) {
            int cc = c + j * 8;
            *(float2*)&smF[r0 * SMF_STRIDE + cc]       = make_float2(acc[mt][j][0], acc[mt][j][1]);
            *(float2*)&smF[(r0 + 8) * SMF_STRIDE + cc] = make_float2(acc[mt][j][2], acc[mt][j][3]);
        }
    }
    __syncthreads();

    // bias + relu + store + BN stats
    {
        int c4 = tid & 31, rg = tid >> 5;
        float4 bv = *(const float4*)(S.bias + c4 * 4);
        float s0=0,s1=0,s2=0,s3=0,q0=0,q1=0,q2=0,q3=0;
#pragma unroll
        for (int it = 0; it < 16; it++) {
            int r = it * 8 + rg;
            int gr = row0 + r;
            if (gr < N5) {
                float4 v = *(float4*)&smF[r * SMF_STRIDE + c4 * 4];
                v.x = fmaxf(v.x + bv.x, 0.f);
                v.y = fmaxf(v.y + bv.y, 0.f);
                v.z = fmaxf(v.z + bv.z, 0.f);
                v.w = fmaxf(v.w + bv.w, 0.f);
                *(float4*)(S.out + (size_t)gr * HD + c4 * 4) = v;
                s0 += v.x; s1 += v.y; s2 += v.z; s3 += v.w;
                q0 += v.x*v.x; q1 += v.y*v.y; q2 += v.z*v.z; q3 += v.w*v.w;
            }
        }
        atomicAdd(&ssum[c4*4+0], s0); atomicAdd(&ssum[c4*4+1], s1);
        atomicAdd(&ssum[c4*4+2], s2); atomicAdd(&ssum[c4*4+3], s3);
        atomicAdd(&ssq[c4*4+0], q0);  atomicAdd(&ssq[c4*4+1], q1);
        atomicAdd(&ssq[c4*4+2], q2);  atomicAdd(&ssq[c4*4+3], q3);
    }
    __syncthreads();
    if (tid < 128) {
        atomicAdd(&S.statsAcc[tid], ssum[tid]);
        atomicAdd(&S.statsAcc[HD + tid], ssq[tid]);
    }
}

// ---------------- pooling: 512 threads, 4-way row split + smem reduce -----------
__global__ __launch_bounds__(512)
void k_pool(const float* __restrict__ xu, const float* __restrict__ xi,
            const int* __restrict__ su, const int* __restrict__ si,
            const float* __restrict__ statsU, const float* __restrict__ gU,
            const float* __restrict__ btU,
            const float* __restrict__ statsI, const float* __restrict__ gI,
            const float* __restrict__ btI,
            float* __restrict__ feats) {
    __shared__ float red[512];
    int g = blockIdx.x;
    int tid = threadIdx.x;
    int c = tid & 127;
    int chunk = tid >> 7;       // 0..3

    int u0 = su[g], u1 = su[g + 1];
    int i0 = si[g], i1 = si[g + 1];
    float sumU = 0.f, sumI = 0.f;
    for (int r = u0 + chunk; r < u1; r += 4) sumU += xu[(size_t)r * HD + c];
    for (int r = i0 + chunk; r < i1; r += 4) sumI += xi[(size_t)r * HD + c];
    red[tid] = sumU;
    __syncthreads();
    if (chunk == 0) sumU = red[c] + red[128 + c] + red[256 + c] + red[384 + c];
    __syncthreads();
    red[tid] = sumI;
    __syncthreads();
    if (chunk == 0) {
        sumI = red[c] + red[128 + c] + red[256 + c] + red[384 + c];
        const float invN = 1.f / (float)N5;
        float mU = statsU[c] * invN;
        float vU = statsU[HD + c] * invN - mU * mU;
        float aU = gU[c] * rsqrtf(fmaxf(vU, 0.f) + BN_EPS);
        float bU = btU[c] - mU * aU;
        float mI = statsI[c] * invN;
        float vI = statsI[HD + c] * invN - mI * mI;
        float aI = gI[c] * rsqrtf(fmaxf(vI, 0.f) + BN_EPS);
        float bI = btI[c] - mI * aI;
        float nu = (float)(u1 - u0), ni = (float)(i1 - i0);
        float cnt = fmaxf(nu + ni, 1.f);
        feats[(size_t)g * HD + c] = (aU * sumU + nu * bU + aI * sumI + ni * bI) / cnt;
    }
}

// ---------------- per-layer classifier heads ------------------------------------
__global__ void k_logits(const float* __restrict__ feats, const float* __restrict__ fcW,
                         const float* __restrict__ fcb, float* __restrict__ logits) {
    int idx = blockIdx.x * blockDim.x + threadIdx.x;
    if (idx >= NL * NG * NC) return;
    int l = idx / (NG * NC);
    int g = (idx / NC) % NG;
    int c = idx % NC;
    const float* f = feats + ((size_t)l * NG + g) * HD;
    const float* w = fcW + ((size_t)l * NC + c) * HD;
    float sum = fcb[l * NC + c];
#pragma unroll
    for (int k = 0; k < HD; k += 4) {
        float4 a = *(const float4*)(f + k);
        float4 b = *(const float4*)(w + k);
        sum += a.x * b.x + a.y * b.y + a.z * b.z + a.w * b.w;
    }
    logits[idx] = sum;
}

// ---------------- host orchestration -------------------------------------------
extern "C" void kernel_launch(void* const* d_in, const int* in_sizes, int n_in,
                              void* d_out, int out_size) {
    const float* x_user    = (const float*)d_in[0];
    const float* x_item    = (const float*)d_in[1];
    const int*   e_u2i     = (const int*)d_in[2];
    const int*   e_i2u     = (const int*)d_in[3];
    const int*   b_user    = (const int*)d_in[4];
    const int*   b_item    = (const int*)d_in[5];
    const float* Wrel_u2i  = (const float*)d_in[6];
    const float* Wroot_u2i = (const float*)d_in[7];
    const float* b_u2i     = (const float*)d_in[8];
    const float* Wrel_i2u  = (const float*)d_in[9];
    const float* Wroot_i2u = (const float*)d_in[10];
    const float* b_i2u     = (const float*)d_in[11];
    const float* bn_g_user = (const float*)d_in[12];
    const float* bn_b_user = (const float*)d_in[13];
    const float* bn_g_item = (const float*)d_in[14];
    const float* bn_b_item = (const float*)d_in[15];
    const float* fc_W      = (const float*)d_in[16];
    const float* fc_b      = (const float*)d_in[17];

    float* out   = (float*)d_out;
    float* feats = out + NL * NG * NC;

    float *xu, *xi, *newu, *newi, *aggu, *aggi, *stats;
    char* wpre;
    int *rowi, *rowu, *col_u2i, *col_i2u, *degi, *degu, *curi, *curu, *su, *si;
    cudaGetSymbolAddress((void**)&xu, g_xu);
    cudaGetSymbolAddress((void**)&xi, g_xi);
    cudaGetSymbolAddress((void**)&newu, g_newu);
    cudaGetSymbolAddress((void**)&newi, g_newi);
    cudaGetSymbolAddress((void**)&aggu, g_aggu);
    cudaGetSymbolAddress((void**)&aggi, g_aggi);
    cudaGetSymbolAddress((void**)&wpre, g_wpre);
    cudaGetSymbolAddress((void**)&stats, g_stats);
    cudaGetSymbolAddress((void**)&rowi, g_rowi);
    cudaGetSymbolAddress((void**)&rowu, g_rowu);
    cudaGetSymbolAddress((void**)&col_u2i, g_col_u2i);
    cudaGetSymbolAddress((void**)&col_i2u, g_col_i2u);
    cudaGetSymbolAddress((void**)&degi, g_degi);
    cudaGetSymbolAddress((void**)&degu, g_degu);
    cudaGetSymbolAddress((void**)&curi, g_curi);
    cudaGetSymbolAddress((void**)&curu, g_curu);
    cudaGetSymbolAddress((void**)&su, g_su);
    cudaGetSymbolAddress((void**)&si, g_si);

    cudaFuncSetAttribute(k_gemm2, cudaFuncAttributeMaxDynamicSharedMemorySize, GEMM_SMEM);

    const int T = 256;
    const int NBLK = CDIV(N5, 128);

    // setup
    k_init<<<CDIV(N5, T), T>>>(stats, degi, degu);
    k_hist2<<<CDIV(2*NE, T), T>>>(e_u2i + NE, e_i2u + NE, degi, degu);
    k_scan2<<<2, 1024>>>(degi, rowi, curi, degu, rowu, curu);
    k_scatter2<<<CDIV(2*NE, T), T>>>(e_u2i, e_i2u, curi, col_u2i, curu, col_i2u);
    k_offsets2<<<CDIV(2*(NG+1), 128), 128>>>(b_user, b_item, su, si);
    k_prepw<<<CDIV(NL*2*2*128*64, T), T>>>(Wrel_u2i, Wroot_u2i, Wrel_i2u, Wroot_i2u, wpre);

    // ---- layers --------------------------------------------------------------
    const float* prevU = x_user;
    const float* prevI = x_item;
    float* bufsU[NL] = { xu, newu, xu };
    float* bufsI[NL] = { xi, newi, xi };

    for (int l = 0; l < NL; l++) {
        float* curU = bufsU[l];
        float* curI = bufsI[l];
        float* stats_u = stats + (size_t)(l*2 + 0) * 2 * HD;
        float* stats_i = stats + (size_t)(l*2 + 1) * 2 * HD;
        const float* pstats_u = (l > 0) ? stats + (size_t)((l-1)*2 + 0) * 2 * HD : stats;
        const float* pstats_i = (l > 0) ? stats + (size_t)((l-1)*2 + 1) * 2 * HD : stats;

        k_agg2<<<CDIV((NI+NU)*32, T), T>>>(rowi, col_u2i, prevU, aggi,
                                           rowu, col_i2u, prevI, aggu);

        GemmSide SI;
        SI.agg = aggi; SI.xprev = prevI;
        SI.wpre = wpre + ((size_t)l * 2 + 0) * 131072;
        SI.bias = b_u2i + (size_t)l*HD;
        SI.out = curI; SI.statsAcc = stats_i; SI.rowp = rowi;
        SI.statsS = pstats_u; SI.gS = bn_g_user; SI.bS = bn_b_user;
        SI.statsD = pstats_i; SI.gD = bn_g_item; SI.bD = bn_b_item;

        GemmSide SU;
        SU.agg = aggu; SU.xprev = prevU;
        SU.wpre = wpre + ((size_t)l * 2 + 1) * 131072;
        SU.bias = b_i2u + (size_t)l*HD;
        SU.out = curU; SU.statsAcc = stats_u; SU.rowp = rowu;
        SU.statsS = pstats_i; SU.gS = bn_g_item; SU.bS = bn_b_item;
        SU.statsD = pstats_u; SU.gD = bn_g_user; SU.bD = bn_b_user;

        k_gemm2<<<2*NBLK, 256, GEMM_SMEM>>>(SI, SU, NBLK, l > 0 ? 1 : 0);

        k_pool<<<NG, 512>>>(curU, curI, su, si,
                            stats_u, bn_g_user, bn_b_user,
                            stats_i, bn_g_item, bn_b_item,
                            feats + (size_t)l*NG*HD);

        prevU = curU; prevI = curI;
    }

    k_logits<<<CDIV(NL*NG*NC, T), T>>>(feats, fc_W, fc_b, out);
}